// round 11
// baseline (speedup 1.0000x reference)
#include <cuda_runtime.h>
#include <cuda_fp16.h>
#include <cstdint>

#define N_NODES_MAX   10000
#define NUM_FEAT      384
#define F_HEAD        128
#define NHEADS        3
#define SPH_DIM       15
#define INV_SQRT_FH   0.08838834764831845f   // 1/sqrt(128)

// Scratch: projected q/k in fp16 (device globals: no allocation allowed)
__device__ __half g_qh[N_NODES_MAX * NUM_FEAT];
__device__ __half g_kh[N_NODES_MAX * NUM_FEAT];

struct __align__(8) Half4 { __half2 a, b; };

// ---------------------------------------------------------------------------
// helpers
// ---------------------------------------------------------------------------
__device__ __forceinline__ uint32_t smem_u32(const void* p) {
    return static_cast<uint32_t>(__cvta_generic_to_shared(p));
}
__device__ __forceinline__ void ldsm_x4(uint32_t addr, uint32_t& r0, uint32_t& r1,
                                        uint32_t& r2, uint32_t& r3) {
    asm volatile("ldmatrix.sync.aligned.m8n8.x4.shared.b16 {%0,%1,%2,%3}, [%4];"
                 : "=r"(r0), "=r"(r1), "=r"(r2), "=r"(r3) : "r"(addr));
}
__device__ __forceinline__ void mma16816(float* c, const uint32_t* a,
                                         const uint32_t* b) {
    asm volatile(
        "mma.sync.aligned.m16n8k16.row.col.f32.f16.f16.f32 "
        "{%0,%1,%2,%3}, {%4,%5,%6,%7}, {%8,%9}, {%0,%1,%2,%3};"
        : "+f"(c[0]), "+f"(c[1]), "+f"(c[2]), "+f"(c[3])
        : "r"(a[0]), "r"(a[1]), "r"(a[2]), "r"(a[3]), "r"(b[0]), "r"(b[1]));
}

// ---------------------------------------------------------------------------
// Projection (validated): fp16 tensor cores, fp32 in, fp16 out.
// Ends with threadfence + PDL trigger so the edge kernel can overlap.
// ---------------------------------------------------------------------------
#define PITCH 136
#define PROJ_SMEM (2 * 128 * PITCH * 2)   // 69632 B

__global__ __launch_bounds__(256, 2) void proj_kernel(
    const float* __restrict__ x,
    const float* __restrict__ Wq,
    const float* __restrict__ Wk,
    float* __restrict__ out, int out_n,
    int n_nodes)
{
    extern __shared__ __align__(16) __half psmem[];
    __half* Xh = psmem;                  // [128][PITCH]
    __half* Wh = psmem + 128 * PITCH;    // [128][PITCH]

    if (blockIdx.y == 0 && blockIdx.z == 0) {
        for (int i = blockIdx.x * 256 + threadIdx.x; i < out_n;
             i += gridDim.x * 256)
            out[i] = 0.0f;
    }

    const int h    = blockIdx.y;
    const int row0 = blockIdx.x * 128;
    const bool is_k = (blockIdx.z != 0);
    const float* __restrict__ Wsrc = (is_k ? Wk : Wq) + h * F_HEAD * F_HEAD;
    __half* __restrict__ o_base = is_k ? g_kh : g_qh;
    const float scale = is_k ? 1.0f : INV_SQRT_FH;

    const int tid  = threadIdx.x;
    const int warp = tid >> 5;
    const int lane = tid & 31;
    const int wm   = (warp & 3) * 32;
    const int wn   = (warp >> 2) * 64;

    #pragma unroll
    for (int t = tid; t < 128 * 32; t += 256) {
        const int r = t >> 5, c = t & 31;
        const int row = row0 + r;
        float4 xv = make_float4(0.f, 0.f, 0.f, 0.f);
        if (row < n_nodes)
            xv = *(const float4*)&x[(size_t)row * NUM_FEAT + h * F_HEAD + c * 4];
        __half2 hx[2];
        hx[0] = __floats2half2_rn(xv.x, xv.y);
        hx[1] = __floats2half2_rn(xv.z, xv.w);
        *(uint2*)&Xh[r * PITCH + c * 4] = *(const uint2*)hx;

        const float4 wv = *(const float4*)&Wsrc[(size_t)r * F_HEAD + c * 4];
        __half2 hw[2];
        hw[0] = __floats2half2_rn(wv.x, wv.y);
        hw[1] = __floats2half2_rn(wv.z, wv.w);
        *(uint2*)&Wh[r * PITCH + c * 4] = *(const uint2*)hw;
    }
    __syncthreads();

    uint32_t a_base[2];
    #pragma unroll
    for (int mi = 0; mi < 2; mi++)
        a_base[mi] = smem_u32(
            &Xh[(wm + mi * 16 + (lane & 15)) * PITCH + (lane >> 4) * 8]);

    uint32_t b_base[4];
    {
        const int nrow = (lane & 7) + ((lane >> 4) << 3);
        const int ksel = ((lane >> 3) & 1) * 8;
        #pragma unroll
        for (int nb = 0; nb < 4; nb++)
            b_base[nb] = smem_u32(&Wh[(wn + nb * 16 + nrow) * PITCH + ksel]);
    }

    float acc[2][8][4];
    #pragma unroll
    for (int mi = 0; mi < 2; mi++)
        #pragma unroll
        for (int ni = 0; ni < 8; ni++)
            #pragma unroll
            for (int c = 0; c < 4; c++) acc[mi][ni][c] = 0.0f;

    #pragma unroll
    for (int ki = 0; ki < 8; ki++) {
        const uint32_t koff = ki * 32;
        uint32_t af[2][4];
        #pragma unroll
        for (int mi = 0; mi < 2; mi++)
            ldsm_x4(a_base[mi] + koff, af[mi][0], af[mi][1], af[mi][2], af[mi][3]);

        uint32_t bf[8][2];
        #pragma unroll
        for (int nb = 0; nb < 4; nb++) {
            uint32_t r0, r1, r2, r3;
            ldsm_x4(b_base[nb] + koff, r0, r1, r2, r3);
            bf[nb * 2 + 0][0] = r0;  bf[nb * 2 + 0][1] = r1;
            bf[nb * 2 + 1][0] = r2;  bf[nb * 2 + 1][1] = r3;
        }

        #pragma unroll
        for (int mi = 0; mi < 2; mi++)
            #pragma unroll
            for (int ni = 0; ni < 8; ni++)
                mma16816(acc[mi][ni], af[mi], bf[ni]);
    }

    #pragma unroll
    for (int mi = 0; mi < 2; mi++) {
        const int ra = row0 + wm + mi * 16 + (lane >> 2);
        const int rb = ra + 8;
        #pragma unroll
        for (int ni = 0; ni < 8; ni++) {
            const int col = h * F_HEAD + wn + ni * 8 + (lane & 3) * 2;
            if (ra < n_nodes)
                *(__half2*)(o_base + (size_t)ra * NUM_FEAT + col) =
                    __floats2half2_rn(acc[mi][ni][0] * scale, acc[mi][ni][1] * scale);
            if (rb < n_nodes)
                *(__half2*)(o_base + (size_t)rb * NUM_FEAT + col) =
                    __floats2half2_rn(acc[mi][ni][2] * scale, acc[mi][ni][3] * scale);
        }
    }

    // Make q/k stores visible, then release the dependent edge grid.
    __threadfence();
    cudaTriggerProgrammaticLaunchCompletion();
}

// ---------------------------------------------------------------------------
// Edge kernel: one warp per edge. PDL: loads independent of proj (w, sph,
// idx, phi) are issued BEFORE cudaGridDependencySynchronize(); the q/k
// gathers (which depend on proj's output) come after.
// ---------------------------------------------------------------------------
__global__ __launch_bounds__(256) void edge_kernel(
    const float* __restrict__ w_ij,
    const float* __restrict__ sph,
    const int*   __restrict__ idx_i,
    const int*   __restrict__ idx_j,
    const float* __restrict__ phi_r,
    const float* __restrict__ phi_chi,
    float* __restrict__ out,
    int n_pairs)
{
    const int e    = (blockIdx.x * blockDim.x + threadIdx.x) >> 5;
    const int lane = threadIdx.x & 31;
    if (e >= n_pairs) {
        cudaGridDependencySynchronize();
        return;
    }

    // ---- independent loads (overlap with proj) ----
    const int ni = idx_i[e];
    const int nj = idx_j[e];
    const float cut = phi_r[e] + phi_chi[e];

    const float4* __restrict__ w4 = (const float4*)(w_ij + (size_t)e * NUM_FEAT);
    float4 wv[NHEADS];
    #pragma unroll
    for (int hh = 0; hh < NHEADS; hh++)
        wv[hh] = __ldcs(&w4[lane + hh * 32]);

    float sv = 0.0f;
    if (lane < SPH_DIM)
        sv = __ldcs(&sph[(size_t)e * SPH_DIM + lane]);

    // ---- wait for proj's q/k ----
    cudaGridDependencySynchronize();

    const Half4* __restrict__ q4 = (const Half4*)(g_qh + (size_t)ni * NUM_FEAT);
    const Half4* __restrict__ k4 = (const Half4*)(g_kh + (size_t)nj * NUM_FEAT);

    float a[NHEADS];
    #pragma unroll
    for (int hh = 0; hh < NHEADS; hh++) {
        const int idx = lane + hh * 32;
        const Half4 qh = q4[idx];
        const Half4 kh = k4[idx];

        const float2 qa = __half22float2(qh.a);
        const float2 qb = __half22float2(qh.b);
        const float2 ka = __half22float2(kh.a);
        const float2 kb = __half22float2(kh.b);

        a[hh] = qa.x * wv[hh].x * ka.x
              + qa.y * wv[hh].y * ka.y
              + qb.x * wv[hh].z * kb.x
              + qb.y * wv[hh].w * kb.y;
    }

    #pragma unroll
    for (int off = 16; off > 0; off >>= 1) {
        #pragma unroll
        for (int hh = 0; hh < NHEADS; hh++)
            a[hh] += __shfl_xor_sync(0xFFFFFFFFu, a[hh], off);
    }

    if (lane < SPH_DIM) {
        const float alpha = (lane < 3 ? a[0] : (lane < 8 ? a[1] : a[2])) * cut;
        atomicAdd(&out[(size_t)ni * SPH_DIM + lane], alpha * sv);
    }
}

// ---------------------------------------------------------------------------
// Launch. Inputs (metadata order):
//  0: chi (unused)  1: sph_ij  2: x  3: w_ij  4: idx_i  5: phi_r_cut
//  6: phi_chi_cut   7: idx_j   8: Wq 9: Wk
// ---------------------------------------------------------------------------
extern "C" void kernel_launch(void* const* d_in, const int* in_sizes, int n_in,
                              void* d_out, int out_size)
{
    const float* sph     = (const float*)d_in[1];
    const float* x       = (const float*)d_in[2];
    const float* w_ij    = (const float*)d_in[3];
    const int*   idx_i   = (const int*)  d_in[4];
    const float* phi_r   = (const float*)d_in[5];
    const float* phi_chi = (const float*)d_in[6];
    const int*   idx_j   = (const int*)  d_in[7];
    const float* Wq      = (const float*)d_in[8];
    const float* Wk      = (const float*)d_in[9];
    float* out = (float*)d_out;

    const int n_nodes = in_sizes[2] / NUM_FEAT;
    const int n_pairs = in_sizes[4];

    cudaFuncSetAttribute(proj_kernel,
                         cudaFuncAttributeMaxDynamicSharedMemorySize,
                         PROJ_SMEM);

    // 1) projections (tensor cores; zero-init folded in; PDL trigger at end)
    dim3 pgrid((n_nodes + 127) / 128, NHEADS, 2);
    proj_kernel<<<pgrid, 256, PROJ_SMEM>>>(x, Wq, Wk, out, out_size, n_nodes);

    // 2) edge attention + scatter, launched with programmatic dependency so
    //    its independent DRAM-stream loads overlap the projection.
    const int warps_per_block = 256 / 32;
    const int eblocks = (n_pairs + warps_per_block - 1) / warps_per_block;

    cudaLaunchConfig_t cfg = {};
    cfg.gridDim  = dim3(eblocks, 1, 1);
    cfg.blockDim = dim3(256, 1, 1);
    cfg.dynamicSmemBytes = 0;
    cfg.stream = 0;
    cudaLaunchAttribute attrs[1];
    attrs[0].id = cudaLaunchAttributeProgrammaticStreamSerialization;
    attrs[0].val.programmaticStreamSerializationAllowed = 1;
    cfg.attrs = attrs;
    cfg.numAttrs = 1;
    cudaLaunchKernelEx(&cfg, edge_kernel,
                       w_ij, sph, idx_i, idx_j, phi_r, phi_chi,
                       out, n_pairs);
}

// round 12
// speedup vs baseline: 1.0319x; 1.0319x over previous
#include <cuda_runtime.h>
#include <cuda_fp16.h>
#include <cstdint>

#define N_NODES_MAX   10000
#define NUM_FEAT      384
#define F_HEAD        128
#define NHEADS        3
#define SPH_DIM       15
#define INV_SQRT_FH   0.08838834764831845f   // 1/sqrt(128)

// Scratch: projected q/k in fp16 (device globals: no allocation allowed)
__device__ __half g_qh[N_NODES_MAX * NUM_FEAT];
__device__ __half g_kh[N_NODES_MAX * NUM_FEAT];

struct __align__(8) Half4 { __half2 a, b; };

// ---------------------------------------------------------------------------
// helpers
// ---------------------------------------------------------------------------
__device__ __forceinline__ uint32_t smem_u32(const void* p) {
    return static_cast<uint32_t>(__cvta_generic_to_shared(p));
}
__device__ __forceinline__ void ldsm_x4(uint32_t addr, uint32_t& r0, uint32_t& r1,
                                        uint32_t& r2, uint32_t& r3) {
    asm volatile("ldmatrix.sync.aligned.m8n8.x4.shared.b16 {%0,%1,%2,%3}, [%4];"
                 : "=r"(r0), "=r"(r1), "=r"(r2), "=r"(r3) : "r"(addr));
}
__device__ __forceinline__ void mma16816(float* c, const uint32_t* a,
                                         const uint32_t* b) {
    asm volatile(
        "mma.sync.aligned.m16n8k16.row.col.f32.f16.f16.f32 "
        "{%0,%1,%2,%3}, {%4,%5,%6,%7}, {%8,%9}, {%0,%1,%2,%3};"
        : "+f"(c[0]), "+f"(c[1]), "+f"(c[2]), "+f"(c[3])
        : "r"(a[0]), "r"(a[1]), "r"(a[2]), "r"(a[3]), "r"(b[0]), "r"(b[1]));
}

// ---------------------------------------------------------------------------
// Projection: fp16 tensor cores, fp32 in, fp16 out. Q and K fused in one
// block: X staged once, Wq MMA -> store q, restage Wk -> store k.
// C-tile 128x128; 8 warps as 4(m) x 2(n). PITCH=136 conflict-free.
// Zero-inits `out` (y==0 blocks).
// ---------------------------------------------------------------------------
#define PITCH 136
#define PROJ_SMEM (2 * 128 * PITCH * 2)   // X + W tiles, bytes (69632)

__global__ __launch_bounds__(256, 2) void proj_kernel(
    const float* __restrict__ x,
    const float* __restrict__ Wq,
    const float* __restrict__ Wk,
    float* __restrict__ out, int out_n,
    int n_nodes)
{
    extern __shared__ __align__(16) __half psmem[];
    __half* Xh = psmem;                  // [128][PITCH]
    __half* Wh = psmem + 128 * PITCH;    // [128][PITCH]

    if (blockIdx.y == 0) {
        for (int i = blockIdx.x * 256 + threadIdx.x; i < out_n;
             i += gridDim.x * 256)
            out[i] = 0.0f;
    }

    const int h    = blockIdx.y;
    const int row0 = blockIdx.x * 128;

    const int tid  = threadIdx.x;
    const int warp = tid >> 5;
    const int lane = tid & 31;
    const int wm   = (warp & 3) * 32;
    const int wn   = (warp >> 2) * 64;

    // ---- stage X once (full K=128), fp32 -> fp16 inline ----
    #pragma unroll
    for (int t = tid; t < 128 * 32; t += 256) {
        const int r = t >> 5, c = t & 31;
        const int row = row0 + r;
        float4 xv = make_float4(0.f, 0.f, 0.f, 0.f);
        if (row < n_nodes)
            xv = *(const float4*)&x[(size_t)row * NUM_FEAT + h * F_HEAD + c * 4];
        __half2 hx[2];
        hx[0] = __floats2half2_rn(xv.x, xv.y);
        hx[1] = __floats2half2_rn(xv.z, xv.w);
        *(uint2*)&Xh[r * PITCH + c * 4] = *(const uint2*)hx;
    }

    // fragment addresses (fixed for both passes)
    uint32_t a_base[2];
    #pragma unroll
    for (int mi = 0; mi < 2; mi++)
        a_base[mi] = smem_u32(
            &Xh[(wm + mi * 16 + (lane & 15)) * PITCH + (lane >> 4) * 8]);

    uint32_t b_base[4];
    {
        const int nrow = (lane & 7) + ((lane >> 4) << 3);
        const int ksel = ((lane >> 3) & 1) * 8;
        #pragma unroll
        for (int nb = 0; nb < 4; nb++)
            b_base[nb] = smem_u32(&Wh[(wn + nb * 16 + nrow) * PITCH + ksel]);
    }

    // ---- two passes: z=0 -> q (Wq, scaled), z=1 -> k (Wk) ----
    #pragma unroll
    for (int z = 0; z < 2; z++) {
        const bool is_k = (z != 0);
        const float* __restrict__ Wsrc = (is_k ? Wk : Wq) + h * F_HEAD * F_HEAD;
        __half* __restrict__ o_base = is_k ? g_kh : g_qh;
        const float scale = is_k ? 1.0f : INV_SQRT_FH;

        if (z == 1) __syncthreads();   // all q-MMA reads of Wh done

        // stage W tile
        #pragma unroll
        for (int t = tid; t < 128 * 32; t += 256) {
            const int r = t >> 5, c = t & 31;
            const float4 wv = *(const float4*)&Wsrc[(size_t)r * F_HEAD + c * 4];
            __half2 hw[2];
            hw[0] = __floats2half2_rn(wv.x, wv.y);
            hw[1] = __floats2half2_rn(wv.z, wv.w);
            *(uint2*)&Wh[r * PITCH + c * 4] = *(const uint2*)hw;
        }
        __syncthreads();

        float acc[2][8][4];
        #pragma unroll
        for (int mi = 0; mi < 2; mi++)
            #pragma unroll
            for (int ni = 0; ni < 8; ni++)
                #pragma unroll
                for (int c = 0; c < 4; c++) acc[mi][ni][c] = 0.0f;

        #pragma unroll
        for (int ki = 0; ki < 8; ki++) {
            const uint32_t koff = ki * 32;
            uint32_t af[2][4];
            #pragma unroll
            for (int mi = 0; mi < 2; mi++)
                ldsm_x4(a_base[mi] + koff, af[mi][0], af[mi][1], af[mi][2], af[mi][3]);

            uint32_t bf[8][2];
            #pragma unroll
            for (int nb = 0; nb < 4; nb++) {
                uint32_t r0, r1, r2, r3;
                ldsm_x4(b_base[nb] + koff, r0, r1, r2, r3);
                bf[nb * 2 + 0][0] = r0;  bf[nb * 2 + 0][1] = r1;
                bf[nb * 2 + 1][0] = r2;  bf[nb * 2 + 1][1] = r3;
            }

            #pragma unroll
            for (int mi = 0; mi < 2; mi++)
                #pragma unroll
                for (int ni = 0; ni < 8; ni++)
                    mma16816(acc[mi][ni], af[mi], bf[ni]);
        }

        #pragma unroll
        for (int mi = 0; mi < 2; mi++) {
            const int ra = row0 + wm + mi * 16 + (lane >> 2);
            const int rb = ra + 8;
            #pragma unroll
            for (int ni = 0; ni < 8; ni++) {
                const int col = h * F_HEAD + wn + ni * 8 + (lane & 3) * 2;
                if (ra < n_nodes)
                    *(__half2*)(o_base + (size_t)ra * NUM_FEAT + col) =
                        __floats2half2_rn(acc[mi][ni][0] * scale, acc[mi][ni][1] * scale);
                if (rb < n_nodes)
                    *(__half2*)(o_base + (size_t)rb * NUM_FEAT + col) =
                        __floats2half2_rn(acc[mi][ni][2] * scale, acc[mi][ni][3] * scale);
            }
        }
    }
}

// ---------------------------------------------------------------------------
// Edge kernel: one warp per edge (best measured).
//   alpha_h = dot(q[i,h,:], w[e,h,:] * k[j,h,:])        (q pre-scaled)
//   alpha_h *= (phi_r[e] + phi_chi[e])
//   out[i, s] += alpha_{head(s)} * sph[e, s]            (atomic)
// ---------------------------------------------------------------------------
__global__ __launch_bounds__(256) void edge_kernel(
    const float* __restrict__ w_ij,
    const float* __restrict__ sph,
    const int*   __restrict__ idx_i,
    const int*   __restrict__ idx_j,
    const float* __restrict__ phi_r,
    const float* __restrict__ phi_chi,
    float* __restrict__ out,
    int n_pairs)
{
    const int e    = (blockIdx.x * blockDim.x + threadIdx.x) >> 5;
    const int lane = threadIdx.x & 31;
    if (e >= n_pairs) return;

    const int ni = idx_i[e];
    const int nj = idx_j[e];

    const Half4*  __restrict__ q4 = (const Half4*)(g_qh + (size_t)ni * NUM_FEAT);
    const Half4*  __restrict__ k4 = (const Half4*)(g_kh + (size_t)nj * NUM_FEAT);
    const float4* __restrict__ w4 = (const float4*)(w_ij + (size_t)e * NUM_FEAT);

    float a[NHEADS];
    #pragma unroll
    for (int hh = 0; hh < NHEADS; hh++) {
        const int idx = lane + hh * 32;
        const Half4  qh = q4[idx];
        const Half4  kh = k4[idx];
        const float4 wv = __ldcs(&w4[idx]);     // one-shot stream

        const float2 qa = __half22float2(qh.a);
        const float2 qb = __half22float2(qh.b);
        const float2 ka = __half22float2(kh.a);
        const float2 kb = __half22float2(kh.b);

        a[hh] = qa.x * wv.x * ka.x
              + qa.y * wv.y * ka.y
              + qb.x * wv.z * kb.x
              + qb.y * wv.w * kb.y;
    }

    #pragma unroll
    for (int off = 16; off > 0; off >>= 1) {
        #pragma unroll
        for (int hh = 0; hh < NHEADS; hh++)
            a[hh] += __shfl_xor_sync(0xFFFFFFFFu, a[hh], off);
    }

    const float cut = phi_r[e] + phi_chi[e];

    if (lane < SPH_DIM) {
        const float alpha = (lane < 3 ? a[0] : (lane < 8 ? a[1] : a[2])) * cut;
        atomicAdd(&out[(size_t)ni * SPH_DIM + lane],
                  alpha * __ldcs(&sph[(size_t)e * SPH_DIM + lane]));
    }
}

// ---------------------------------------------------------------------------
// Launch. Inputs (metadata order):
//  0: chi (unused)  1: sph_ij  2: x  3: w_ij  4: idx_i  5: phi_r_cut
//  6: phi_chi_cut   7: idx_j   8: Wq 9: Wk
// ---------------------------------------------------------------------------
extern "C" void kernel_launch(void* const* d_in, const int* in_sizes, int n_in,
                              void* d_out, int out_size)
{
    const float* sph     = (const float*)d_in[1];
    const float* x       = (const float*)d_in[2];
    const float* w_ij    = (const float*)d_in[3];
    const int*   idx_i   = (const int*)  d_in[4];
    const float* phi_r   = (const float*)d_in[5];
    const float* phi_chi = (const float*)d_in[6];
    const int*   idx_j   = (const int*)  d_in[7];
    const float* Wq      = (const float*)d_in[8];
    const float* Wk      = (const float*)d_in[9];
    float* out = (float*)d_out;

    const int n_nodes = in_sizes[2] / NUM_FEAT;
    const int n_pairs = in_sizes[4];

    cudaFuncSetAttribute(proj_kernel,
                         cudaFuncAttributeMaxDynamicSharedMemorySize,
                         PROJ_SMEM);

    // 1) projections: q AND k per block (x staged once; zero-init folded in)
    dim3 pgrid((n_nodes + 127) / 128, NHEADS, 1);
    proj_kernel<<<pgrid, 256, PROJ_SMEM>>>(x, Wq, Wk, out, out_size, n_nodes);

    // 2) edge attention + scatter (1 warp per edge)
    const int warps_per_block = 256 / 32;
    const int eblocks = (n_pairs + warps_per_block - 1) / warps_per_block;
    edge_kernel<<<eblocks, 256>>>(w_ij, sph, idx_i, idx_j, phi_r, phi_chi,
                                  out, n_pairs);
}

// round 13
// speedup vs baseline: 1.0621x; 1.0292x over previous
#include <cuda_runtime.h>
#include <cuda_fp16.h>
#include <cstdint>

#define N_NODES_MAX   10000
#define NUM_FEAT      384
#define F_HEAD        128
#define NHEADS        3
#define SPH_DIM       15
#define INV_SQRT_FH   0.08838834764831845f   // 1/sqrt(128)

// Scratch: projected q/k in fp16 (device globals: no allocation allowed)
__device__ __half g_qh[N_NODES_MAX * NUM_FEAT];
__device__ __half g_kh[N_NODES_MAX * NUM_FEAT];

struct __align__(8) Half4 { __half2 a, b; };

// ---------------------------------------------------------------------------
// helpers
// ---------------------------------------------------------------------------
__device__ __forceinline__ uint32_t smem_u32(const void* p) {
    return static_cast<uint32_t>(__cvta_generic_to_shared(p));
}
__device__ __forceinline__ void ldsm_x4(uint32_t addr, uint32_t& r0, uint32_t& r1,
                                        uint32_t& r2, uint32_t& r3) {
    asm volatile("ldmatrix.sync.aligned.m8n8.x4.shared.b16 {%0,%1,%2,%3}, [%4];"
                 : "=r"(r0), "=r"(r1), "=r"(r2), "=r"(r3) : "r"(addr));
}
__device__ __forceinline__ void mma16816(float* c, const uint32_t* a,
                                         const uint32_t* b) {
    asm volatile(
        "mma.sync.aligned.m16n8k16.row.col.f32.f16.f16.f32 "
        "{%0,%1,%2,%3}, {%4,%5,%6,%7}, {%8,%9}, {%0,%1,%2,%3};"
        : "+f"(c[0]), "+f"(c[1]), "+f"(c[2]), "+f"(c[3])
        : "r"(a[0]), "r"(a[1]), "r"(a[2]), "r"(a[3]), "r"(b[0]), "r"(b[1]));
}

// ---------------------------------------------------------------------------
// Projection: fp16 tensor cores, fp32 in, fp16 out. Q and K fused in one
// block (X staged once). PDL trigger fired at ENTRY so the dependent edge
// grid launches immediately and overlaps its independent DRAM loads with
// this kernel's compute. cudaGridDependencySynchronize() in the edge kernel
// provides the completion/visibility guarantee for q/k.
// ---------------------------------------------------------------------------
#define PITCH 136
#define PROJ_SMEM (2 * 128 * PITCH * 2)   // X + W tiles, bytes (69632)

__global__ __launch_bounds__(256, 2) void proj_kernel(
    const float* __restrict__ x,
    const float* __restrict__ Wq,
    const float* __restrict__ Wk,
    float* __restrict__ out, int out_n,
    int n_nodes)
{
    // Release the dependent edge grid NOW (it self-gates on q/k via
    // cudaGridDependencySynchronize). This creates the overlap window.
    cudaTriggerProgrammaticLaunchCompletion();

    extern __shared__ __align__(16) __half psmem[];
    __half* Xh = psmem;                  // [128][PITCH]
    __half* Wh = psmem + 128 * PITCH;    // [128][PITCH]

    if (blockIdx.y == 0) {
        for (int i = blockIdx.x * 256 + threadIdx.x; i < out_n;
             i += gridDim.x * 256)
            out[i] = 0.0f;
    }

    const int h    = blockIdx.y;
    const int row0 = blockIdx.x * 128;

    const int tid  = threadIdx.x;
    const int warp = tid >> 5;
    const int lane = tid & 31;
    const int wm   = (warp & 3) * 32;
    const int wn   = (warp >> 2) * 64;

    // ---- stage X once (full K=128), fp32 -> fp16 inline ----
    #pragma unroll
    for (int t = tid; t < 128 * 32; t += 256) {
        const int r = t >> 5, c = t & 31;
        const int row = row0 + r;
        float4 xv = make_float4(0.f, 0.f, 0.f, 0.f);
        if (row < n_nodes)
            xv = *(const float4*)&x[(size_t)row * NUM_FEAT + h * F_HEAD + c * 4];
        __half2 hx[2];
        hx[0] = __floats2half2_rn(xv.x, xv.y);
        hx[1] = __floats2half2_rn(xv.z, xv.w);
        *(uint2*)&Xh[r * PITCH + c * 4] = *(const uint2*)hx;
    }

    uint32_t a_base[2];
    #pragma unroll
    for (int mi = 0; mi < 2; mi++)
        a_base[mi] = smem_u32(
            &Xh[(wm + mi * 16 + (lane & 15)) * PITCH + (lane >> 4) * 8]);

    uint32_t b_base[4];
    {
        const int nrow = (lane & 7) + ((lane >> 4) << 3);
        const int ksel = ((lane >> 3) & 1) * 8;
        #pragma unroll
        for (int nb = 0; nb < 4; nb++)
            b_base[nb] = smem_u32(&Wh[(wn + nb * 16 + nrow) * PITCH + ksel]);
    }

    // ---- two passes: z=0 -> q (Wq, scaled), z=1 -> k (Wk) ----
    #pragma unroll
    for (int z = 0; z < 2; z++) {
        const bool is_k = (z != 0);
        const float* __restrict__ Wsrc = (is_k ? Wk : Wq) + h * F_HEAD * F_HEAD;
        __half* __restrict__ o_base = is_k ? g_kh : g_qh;
        const float scale = is_k ? 1.0f : INV_SQRT_FH;

        if (z == 1) __syncthreads();   // all q-MMA reads of Wh done

        #pragma unroll
        for (int t = tid; t < 128 * 32; t += 256) {
            const int r = t >> 5, c = t & 31;
            const float4 wv = *(const float4*)&Wsrc[(size_t)r * F_HEAD + c * 4];
            __half2 hw[2];
            hw[0] = __floats2half2_rn(wv.x, wv.y);
            hw[1] = __floats2half2_rn(wv.z, wv.w);
            *(uint2*)&Wh[r * PITCH + c * 4] = *(const uint2*)hw;
        }
        __syncthreads();

        float acc[2][8][4];
        #pragma unroll
        for (int mi = 0; mi < 2; mi++)
            #pragma unroll
            for (int ni = 0; ni < 8; ni++)
                #pragma unroll
                for (int c = 0; c < 4; c++) acc[mi][ni][c] = 0.0f;

        #pragma unroll
        for (int ki = 0; ki < 8; ki++) {
            const uint32_t koff = ki * 32;
            uint32_t af[2][4];
            #pragma unroll
            for (int mi = 0; mi < 2; mi++)
                ldsm_x4(a_base[mi] + koff, af[mi][0], af[mi][1], af[mi][2], af[mi][3]);

            uint32_t bf[8][2];
            #pragma unroll
            for (int nb = 0; nb < 4; nb++) {
                uint32_t r0, r1, r2, r3;
                ldsm_x4(b_base[nb] + koff, r0, r1, r2, r3);
                bf[nb * 2 + 0][0] = r0;  bf[nb * 2 + 0][1] = r1;
                bf[nb * 2 + 1][0] = r2;  bf[nb * 2 + 1][1] = r3;
            }

            #pragma unroll
            for (int mi = 0; mi < 2; mi++)
                #pragma unroll
                for (int ni = 0; ni < 8; ni++)
                    mma16816(acc[mi][ni], af[mi], bf[ni]);
        }

        #pragma unroll
        for (int mi = 0; mi < 2; mi++) {
            const int ra = row0 + wm + mi * 16 + (lane >> 2);
            const int rb = ra + 8;
            #pragma unroll
            for (int ni = 0; ni < 8; ni++) {
                const int col = h * F_HEAD + wn + ni * 8 + (lane & 3) * 2;
                if (ra < n_nodes)
                    *(__half2*)(o_base + (size_t)ra * NUM_FEAT + col) =
                        __floats2half2_rn(acc[mi][ni][0] * scale, acc[mi][ni][1] * scale);
                if (rb < n_nodes)
                    *(__half2*)(o_base + (size_t)rb * NUM_FEAT + col) =
                        __floats2half2_rn(acc[mi][ni][2] * scale, acc[mi][ni][3] * scale);
            }
        }
    }
}

// ---------------------------------------------------------------------------
// Edge kernel: one warp per edge. Independent loads (w, sph, idx, phi)
// issued BEFORE cudaGridDependencySynchronize(); q/k gathers after.
// ---------------------------------------------------------------------------
__global__ __launch_bounds__(256) void edge_kernel(
    const float* __restrict__ w_ij,
    const float* __restrict__ sph,
    const int*   __restrict__ idx_i,
    const int*   __restrict__ idx_j,
    const float* __restrict__ phi_r,
    const float* __restrict__ phi_chi,
    float* __restrict__ out,
    int n_pairs)
{
    const int e    = (blockIdx.x * blockDim.x + threadIdx.x) >> 5;
    const int lane = threadIdx.x & 31;
    if (e >= n_pairs) return;

    // ---- independent loads (overlap with proj) ----
    const int ni = idx_i[e];
    const int nj = idx_j[e];
    const float cut = phi_r[e] + phi_chi[e];

    const float4* __restrict__ w4 = (const float4*)(w_ij + (size_t)e * NUM_FEAT);
    float4 wv[NHEADS];
    #pragma unroll
    for (int hh = 0; hh < NHEADS; hh++)
        wv[hh] = __ldcs(&w4[lane + hh * 32]);

    float sv = 0.0f;
    if (lane < SPH_DIM)
        sv = __ldcs(&sph[(size_t)e * SPH_DIM + lane]);

    // ---- wait for proj grid completion (q/k visible after this) ----
    cudaGridDependencySynchronize();

    const Half4* __restrict__ q4 = (const Half4*)(g_qh + (size_t)ni * NUM_FEAT);
    const Half4* __restrict__ k4 = (const Half4*)(g_kh + (size_t)nj * NUM_FEAT);

    float a[NHEADS];
    #pragma unroll
    for (int hh = 0; hh < NHEADS; hh++) {
        const int idx = lane + hh * 32;
        const Half4 qh = q4[idx];
        const Half4 kh = k4[idx];

        const float2 qa = __half22float2(qh.a);
        const float2 qb = __half22float2(qh.b);
        const float2 ka = __half22float2(kh.a);
        const float2 kb = __half22float2(kh.b);

        a[hh] = qa.x * wv[hh].x * ka.x
              + qa.y * wv[hh].y * ka.y
              + qb.x * wv[hh].z * kb.x
              + qb.y * wv[hh].w * kb.y;
    }

    #pragma unroll
    for (int off = 16; off > 0; off >>= 1) {
        #pragma unroll
        for (int hh = 0; hh < NHEADS; hh++)
            a[hh] += __shfl_xor_sync(0xFFFFFFFFu, a[hh], off);
    }

    if (lane < SPH_DIM) {
        const float alpha = (lane < 3 ? a[0] : (lane < 8 ? a[1] : a[2])) * cut;
        atomicAdd(&out[(size_t)ni * SPH_DIM + lane], alpha * sv);
    }
}

// ---------------------------------------------------------------------------
// Launch. Inputs (metadata order):
//  0: chi (unused)  1: sph_ij  2: x  3: w_ij  4: idx_i  5: phi_r_cut
//  6: phi_chi_cut   7: idx_j   8: Wq 9: Wk
// ---------------------------------------------------------------------------
extern "C" void kernel_launch(void* const* d_in, const int* in_sizes, int n_in,
                              void* d_out, int out_size)
{
    const float* sph     = (const float*)d_in[1];
    const float* x       = (const float*)d_in[2];
    const float* w_ij    = (const float*)d_in[3];
    const int*   idx_i   = (const int*)  d_in[4];
    const float* phi_r   = (const float*)d_in[5];
    const float* phi_chi = (const float*)d_in[6];
    const int*   idx_j   = (const int*)  d_in[7];
    const float* Wq      = (const float*)d_in[8];
    const float* Wk      = (const float*)d_in[9];
    float* out = (float*)d_out;

    const int n_nodes = in_sizes[2] / NUM_FEAT;
    const int n_pairs = in_sizes[4];

    cudaFuncSetAttribute(proj_kernel,
                         cudaFuncAttributeMaxDynamicSharedMemorySize,
                         PROJ_SMEM);

    // 1) projections: q AND k per block; PDL trigger at entry
    dim3 pgrid((n_nodes + 127) / 128, NHEADS, 1);
    proj_kernel<<<pgrid, 256, PROJ_SMEM>>>(x, Wq, Wk, out, out_size, n_nodes);

    // 2) edge attention + scatter, PDL-dependent launch: starts while proj
    //    runs, overlapping its independent DRAM-stream loads.
    const int warps_per_block = 256 / 32;
    const int eblocks = (n_pairs + warps_per_block - 1) / warps_per_block;

    cudaLaunchConfig_t cfg = {};
    cfg.gridDim  = dim3(eblocks, 1, 1);
    cfg.blockDim = dim3(256, 1, 1);
    cfg.dynamicSmemBytes = 0;
    cfg.stream = 0;
    cudaLaunchAttribute attrs[1];
    attrs[0].id = cudaLaunchAttributeProgrammaticStreamSerialization;
    attrs[0].val.programmaticStreamSerializationAllowed = 1;
    cfg.attrs = attrs;
    cfg.numAttrs = 1;
    cudaLaunchKernelEx(&cfg, edge_kernel,
                       w_ij, sph, idx_i, idx_j, phi_r, phi_chi,
                       out, n_pairs);
}